// round 15
// baseline (speedup 1.0000x reference)
#include <cuda_runtime.h>
#include <cuda_fp16.h>
#include <cstdint>

// ---------------------------------------------------------------------------
// Problem constants
// ---------------------------------------------------------------------------
#define K_DIM 4096
#define N_DIM 11008
#define M_DIM 8192
#define NGC   (N_DIM / 8)          // packed int32 per K row

// GEMM tiling
#define BM 128
#define BN 128
#define BK 64
#define KT (K_DIM / BK)            // 64 k-iterations
#define NSTAGES 3
#define STAGE_A_BYTES (BM * BK * 2)    // 16384
#define STAGE_B_BYTES (BN * BK * 2)    // 16384
#define SMEM_A 0
#define SMEM_B (NSTAGES * STAGE_A_BYTES)                  // 49152
#define SMEM_COEF (SMEM_B + NSTAGES * STAGE_B_BYTES)      // 98304
#define SMEM_TOTAL (SMEM_COEF + 3 * BN * 4)               // 99840

#define NT_TILES (N_DIM / BN)      // 86
#define MT_TILES (M_DIM / BM)      // 64
#define NTILES (MT_TILES * NT_TILES)   // 5504
#define GROUP_M 8
#define GRID_PERSIST 296           // 2 CTAs per SM

#define UNPACK_BLOCKS ((N_DIM / 256) * (K_DIM / 64))   // 43 * 64 = 2752
#define NB_BLOCKS (N_DIM / 256)                        // 43

// ---------------------------------------------------------------------------
// Device scratch (no allocations allowed in kernel_launch)
// ---------------------------------------------------------------------------
__device__ __align__(1024) __half g_Wt[(size_t)N_DIM * K_DIM];   // W^T [N,K] fp16
__device__ __align__(1024) __half g_Xh[(size_t)M_DIM * K_DIM];   // X   [M,K] fp16
__device__ float g_rowsum[M_DIM];

// ---------------------------------------------------------------------------
// PTX helpers (generic sm_80-level PTX only: compiles under compute_103)
// ---------------------------------------------------------------------------
__device__ __forceinline__ uint32_t smem_u32(const void* p) {
    uint32_t a;
    asm("{ .reg .u64 t; cvta.to.shared.u64 t, %1; cvt.u32.u64 %0, t; }"
        : "=r"(a) : "l"(p));
    return a;
}

__device__ __forceinline__ void cp_async16(uint32_t dst, const void* src) {
    asm volatile("cp.async.cg.shared.global [%0], [%1], 16;"
                 :: "r"(dst), "l"(__cvta_generic_to_global(src)) : "memory");
}
__device__ __forceinline__ void cp_commit() {
    asm volatile("cp.async.commit_group;" ::: "memory");
}
template <int N>
__device__ __forceinline__ void cp_wait() {
    asm volatile("cp.async.wait_group %0;" :: "n"(N) : "memory");
}

__device__ __forceinline__ void ldsm_x4(uint32_t& r0, uint32_t& r1, uint32_t& r2,
                                        uint32_t& r3, uint32_t addr) {
    asm volatile("ldmatrix.sync.aligned.m8n8.x4.shared.b16 {%0,%1,%2,%3}, [%4];"
                 : "=r"(r0), "=r"(r1), "=r"(r2), "=r"(r3) : "r"(addr));
}

__device__ __forceinline__ void mma16816(float* c, const uint32_t* a, const uint32_t* b) {
    asm volatile(
        "mma.sync.aligned.m16n8k16.row.col.f32.f16.f16.f32 "
        "{%0,%1,%2,%3}, {%4,%5,%6,%7}, {%8,%9}, {%0,%1,%2,%3};"
        : "+f"(c[0]), "+f"(c[1]), "+f"(c[2]), "+f"(c[3])
        : "r"(a[0]), "r"(a[1]), "r"(a[2]), "r"(a[3]), "r"(b[0]), "r"(b[1]));
}

// ---------------------------------------------------------------------------
// Kernel 0 (fused prep): blocks [0, UNPACK_BLOCKS) unpack int4 weights ->
// g_Wt[N][K] fp16; blocks [UNPACK_BLOCKS, +M_DIM) convert X fp32 -> fp16 +
// rowsum of the rounded values.
// ---------------------------------------------------------------------------
__global__ __launch_bounds__(256) void prep_kernel(const int* __restrict__ qw,
                                                   const float* __restrict__ x) {
    __shared__ int w[64][32];          // 8KB (unpack branch only)
    __shared__ float ws[8];

    if (blockIdx.x < UNPACK_BLOCKS) {
        const int bx = blockIdx.x % NB_BLOCKS;
        const int by = blockIdx.x / NB_BLOCKS;
        const int n0 = bx * 256;
        const int k0 = by * 64;
        const int ngBase = n0 >> 3;
        const int lane = threadIdx.x & 31;
        const int wq = threadIdx.x >> 5;

#pragma unroll
        for (int i = 0; i < 8; i++) {
            const int k = wq * 8 + i;
            w[k][lane] = qw[(size_t)(k0 + k) * NGC + ngBase + lane];
        }
        __syncthreads();

        const int t = threadIdx.x;     // owns output row n0 + t
        const int col = t >> 3;
        const int sh = (t & 7) * 4;
        __half2 buf[32];
#pragma unroll
        for (int k = 0; k < 64; k += 2) {
            const uint32_t q0 = ((uint32_t)w[k][col] >> sh) & 0xF;
            const uint32_t q1 = ((uint32_t)w[k + 1][col] >> sh) & 0xF;
            buf[k >> 1] = __floats2half2_rn((float)q0, (float)q1);
        }
        uint4* dst = reinterpret_cast<uint4*>(g_Wt + (size_t)(n0 + t) * K_DIM + k0);
        const uint4* src = reinterpret_cast<const uint4*>(buf);
#pragma unroll
        for (int i = 0; i < 8; i++) dst[i] = src[i];
    } else {
        const int m = blockIdx.x - UNPACK_BLOCKS;
        const float4* xr = reinterpret_cast<const float4*>(x + (size_t)m * K_DIM);
        uint2* xo = reinterpret_cast<uint2*>(g_Xh + (size_t)m * K_DIM);
        float sum = 0.f;
#pragma unroll
        for (int i = 0; i < 4; i++) {
            const int j = threadIdx.x + i * 256;
            const float4 v = xr[j];
            __half2 a = __floats2half2_rn(v.x, v.y);
            __half2 b = __floats2half2_rn(v.z, v.w);
            uint2 u;
            u.x = *reinterpret_cast<uint32_t*>(&a);
            u.y = *reinterpret_cast<uint32_t*>(&b);
            xo[j] = u;
            const float2 fa = __half22float2(a);
            const float2 fb = __half22float2(b);
            sum += (fa.x + fa.y) + (fb.x + fb.y);
        }
#pragma unroll
        for (int off = 16; off; off >>= 1) sum += __shfl_xor_sync(0xffffffffu, sum, off);
        if ((threadIdx.x & 31) == 0) ws[threadIdx.x >> 5] = sum;
        __syncthreads();
        if (threadIdx.x == 0) {
            float s = 0.f;
#pragma unroll
            for (int wi = 0; wi < 8; wi++) s += ws[wi];
            g_rowsum[m] = s;
        }
    }
}

// ---------------------------------------------------------------------------
// Kernel 1: PERSISTENT mma.sync fp16 GEMM, 296 CTAs (2/SM), continuous
// cross-tile cp.async stage ring, hand-interleaved inner loop.
// SYNC FIX vs previous revision: the single per-iter __syncthreads now sits
// at the START of ks3, immediately after cp_wait<1> — each thread first
// retires its own async groups, the barrier then PUBLISHES all threads'
// copies, and only then does the tail prefetch ldmatrix read the next
// stage. The same barrier orders all ldsm reads of the current stage
// (ks0-ks2) before the next iteration's refill writes. One barrier/iter.
// Epilogue: out = acc*scale - rowsum*scale*zp + bias
// ---------------------------------------------------------------------------
__global__ __launch_bounds__(128, 2) void gemm_kernel(
    const float* __restrict__ scales,
    const int*   __restrict__ qzeros,
    const float* __restrict__ bias,
    float* __restrict__ out)
{
    extern __shared__ char smem[];
    const uint32_t sb = smem_u32(smem);
    const int tid = threadIdx.x;
    const int lane = tid & 31;
    const int wid = tid >> 5;           // 0..3

    float* sS = reinterpret_cast<float*>(smem + SMEM_COEF);
    float* sZ = sS + BN;
    float* sBi = sZ + BN;

    // cp.async indices: 128 threads, 16B chunks; rows of 128B (8 chunks)
    const int ldRow = tid >> 3;          // 0..15
    const int ldChunk = tid & 7;         // 0..7
    const uint32_t swz = (uint32_t)((ldChunk ^ (ldRow & 7)) << 4);

    // Warp tiling: 2 (m) x 2 (n) warps; warp tile 64 x 64
    const int warp_m = wid >> 1;         // 0..1
    const int warp_n = wid & 1;          // 0..1
    const int rowA0 = warp_m * 64 + (lane & 15);
    const int rowB0 = warp_n * 64 + (lane & 15);
    const int halfSel = lane >> 4;

    const uint32_t aAddrBase = sb + SMEM_A + rowA0 * 128;
    const uint32_t bAddrBase = sb + SMEM_B + rowB0 * 128;
    const uint32_t xorA = (uint32_t)(rowA0 & 7);
    const uint32_t xorB = (uint32_t)(rowB0 & 7);

    float acc[4][8][4];
    uint32_t afr[2][4][4];
    uint32_t bfr[2][8][2];

    // tile index -> (mBase, nBase) with GROUP_M swizzle
    auto tileMN = [&](int p, int& mB, int& nB) {
        const int group = p / (GROUP_M * NT_TILES);
        const int rem = p - group * (GROUP_M * NT_TILES);
        const int mt = group * GROUP_M + (rem & (GROUP_M - 1));
        const int nt = rem >> 3;
        mB = mt * BM;
        nB = nt * BN;
    };
    auto coefLoad = [&](int nB) {
        const int n = nB + tid;
        const float sc = scales[n];
        const int zq = qzeros[n >> 3];
        const int zp = (zq >> ((n & 7) * 4)) & 0xF;
        sS[tid] = sc;
        sZ[tid] = sc * (float)zp;
        sBi[tid] = bias[n];
    };

    // Single-piece fragment loaders
    auto ldsmA1 = [&](int buf, uint32_t aSt, int ks, int mi) {
        const uint32_t c = (uint32_t)(ks * 2 + halfSel);
        ldsm_x4(afr[buf][mi][0], afr[buf][mi][1], afr[buf][mi][2],
                afr[buf][mi][3], aSt + mi * 16 * 128 + ((c ^ xorA) << 4));
    };
    auto ldsmB1 = [&](int buf, uint32_t bSt, int ks, int ni) {
        const uint32_t c = (uint32_t)(ks * 2 + halfSel);
        uint32_t r0, r1, r2, r3;
        ldsm_x4(r0, r1, r2, r3, bSt + ni * 16 * 128 + ((c ^ xorB) << 4));
        bfr[buf][ni * 2][0] = r0;     bfr[buf][ni * 2][1] = r2;
        bfr[buf][ni * 2 + 1][0] = r1; bfr[buf][ni * 2 + 1][1] = r3;
    };
    // One 16B chunk of a stage fill (i = 0..7 A, 8..15 B)
    auto chunk = [&](const __half* iA, const __half* iB, int st, int gk, int i) {
        if (i < 8) {
            const int row = ldRow + i * 16;
            cp_async16(sb + SMEM_A + st * STAGE_A_BYTES + row * 128 + swz,
                       iA + (size_t)row * K_DIM + gk);
        } else {
            const int row = ldRow + (i - 8) * 16;
            cp_async16(sb + SMEM_B + st * STAGE_B_BYTES + row * 128 + swz,
                       iB + (size_t)row * K_DIM + gk);
        }
    };
    auto mmaRow = [&](int cb, int mi) {
#pragma unroll
        for (int nj = 0; nj < 8; nj++)
            mma16816(acc[mi][nj], afr[cb][mi], bfr[cb][nj]);
    };

    // ---- First tile setup ----
    int pid = blockIdx.x;
    int mBase, nBase;
    tileMN(pid, mBase, nBase);
    const __half* gA = g_Xh + (size_t)mBase * K_DIM;
    const __half* gB = g_Wt + (size_t)nBase * K_DIM;
    coefLoad(nBase);

    // Cold prologue (once per CTA): fill stages 0 and 1, preload fragments
#pragma unroll
    for (int i = 0; i < 16; i++) chunk(gA, gB, 0, ldChunk * 8, i);
    cp_commit();
#pragma unroll
    for (int i = 0; i < 16; i++) chunk(gA, gB, 1, BK + ldChunk * 8, i);
    cp_commit();
    cp_wait<1>();
    __syncthreads();                     // publish stage 0 to all threads
#pragma unroll
    for (int mi = 0; mi < 4; mi++) ldsmA1(0, aAddrBase, 0, mi);
#pragma unroll
    for (int ni = 0; ni < 4; ni++) ldsmB1(0, bAddrBase, 0, ni);

    int stRead = 0;
    int stWrite = NSTAGES - 1;

    while (true) {
        const int nextPid = pid + (int)gridDim.x;
        const bool hasNext = nextPid < NTILES;
        int mB2 = mBase, nB2 = nBase;
        const __half* gA2 = gA;
        const __half* gB2 = gB;
        if (hasNext) {
            tileMN(nextPid, mB2, nB2);
            gA2 = g_Xh + (size_t)mB2 * K_DIM;
            gB2 = g_Wt + (size_t)nB2 * K_DIM;
        }

#pragma unroll
        for (int mi = 0; mi < 4; mi++)
#pragma unroll
            for (int nj = 0; nj < 8; nj++)
#pragma unroll
                for (int e = 0; e < 4; e++) acc[mi][nj][e] = 0.f;

        for (int kt = 0; kt < KT; kt++) {
            const uint32_t aSt = aAddrBase + stRead * STAGE_A_BYTES;
            const uint32_t bSt = bAddrBase + stRead * STAGE_B_BYTES;
            const int stNext = (stRead == NSTAGES - 1) ? 0 : stRead + 1;
            const uint32_t aNx = aAddrBase + stNext * STAGE_A_BYTES;
            const uint32_t bNx = bAddrBase + stNext * STAGE_B_BYTES;

            const int pf = kt + 2;
            const bool curIss = (pf < KT);
            const bool doIss = curIss || hasNext;
            const __half* iA = curIss ? gA : gA2;
            const __half* iB = curIss ? gB : gB2;
            const int gkk = (curIss ? pf : pf - KT) * BK + ldChunk * 8;
            const bool doTail = (kt + 1 < KT) || hasNext;

            // ks0: MMA(buf0) (registers preloaded); ldsm(ks1); A chunks
#pragma unroll
            for (int mi = 0; mi < 4; mi++) {
                mmaRow(0, mi);
                ldsmA1(1, aSt, 1, mi);
                ldsmB1(1, bSt, 1, mi);
                if (doIss) { chunk(iA, iB, stWrite, gkk, 2 * mi);
                             chunk(iA, iB, stWrite, gkk, 2 * mi + 1); }
            }
            // ks1: MMA(buf1); ldsm(ks2); B chunks
#pragma unroll
            for (int mi = 0; mi < 4; mi++) {
                mmaRow(1, mi);
                ldsmA1(0, aSt, 2, mi);
                ldsmB1(0, bSt, 2, mi);
                if (doIss) { chunk(iA, iB, stWrite, gkk, 8 + 2 * mi);
                             chunk(iA, iB, stWrite, gkk, 9 + 2 * mi); }
            }
            cp_commit();                 // one group per iter (may be empty)
            // ks2: MMA(buf0); ldsm(ks3)
#pragma unroll
            for (int mi = 0; mi < 4; mi++) {
                mmaRow(0, mi);
                ldsmA1(1, aSt, 3, mi);
                ldsmB1(1, bSt, 3, mi);
            }

            // --- THE barrier: retire own async groups, publish everyone's.
            // After this point the stage for kt+1 (or next tile kt0) is
            // fully visible, and all reads of stage stRead are complete, so
            // the next iteration may overwrite it without a top barrier.
            cp_wait<1>();
            __syncthreads();

            // ks3: MMA(buf1); tail-prefetch (next kt or next tile) -> buf0
            mmaRow(1, 0);
            if (doTail) { ldsmA1(0, aNx, 0, 0); ldsmB1(0, bNx, 0, 0); }
#pragma unroll
            for (int mi = 1; mi < 4; mi++) {
                mmaRow(1, mi);
                if (doTail) { ldsmA1(0, aNx, 0, mi); ldsmB1(0, bNx, 0, mi); }
            }

            stRead = stNext;
            stWrite = (stWrite == NSTAGES - 1) ? 0 : stWrite + 1;
        }

        // ---- Epilogue for current tile ----
        {
            const int groupRow = lane >> 2;
            const int colPair = (lane & 3) * 2;
#pragma unroll
            for (int mi = 0; mi < 4; mi++) {
                const int r0 = mBase + warp_m * 64 + mi * 16 + groupRow;
                const int r1 = r0 + 8;
                const float rs0 = g_rowsum[r0];
                const float rs1 = g_rowsum[r1];
                float* o0 = out + (size_t)r0 * N_DIM + nBase;
                float* o1 = out + (size_t)r1 * N_DIM + nBase;
#pragma unroll
                for (int nj = 0; nj < 8; nj++) {
                    const int c = warp_n * 64 + nj * 8 + colPair;
                    float2 v0, v1;
                    v0.x = acc[mi][nj][0] * sS[c]     - rs0 * sZ[c]     + sBi[c];
                    v0.y = acc[mi][nj][1] * sS[c + 1] - rs0 * sZ[c + 1] + sBi[c + 1];
                    v1.x = acc[mi][nj][2] * sS[c]     - rs1 * sZ[c]     + sBi[c];
                    v1.y = acc[mi][nj][3] * sS[c + 1] - rs1 * sZ[c + 1] + sBi[c + 1];
                    *reinterpret_cast<float2*>(o0 + c) = v0;
                    *reinterpret_cast<float2*>(o1 + c) = v1;
                }
            }
        }
        __syncthreads();                 // all epilogue coef reads done

        if (!hasNext) break;
        pid = nextPid;
        mBase = mB2; nBase = nB2; gA = gA2; gB = gB2;
        coefLoad(nBase);                 // next tile's coefficients
    }
    cp_wait<0>();
}

// ---------------------------------------------------------------------------
// Host
// ---------------------------------------------------------------------------
extern "C" void kernel_launch(void* const* d_in, const int* in_sizes, int n_in,
                              void* d_out, int out_size) {
    const float* x       = (const float*)d_in[0];
    const int*   qweight = (const int*)d_in[1];
    const float* scales  = (const float*)d_in[2];
    const int*   qzeros  = (const int*)d_in[3];
    const float* bias    = (const float*)d_in[4];
    float* out = (float*)d_out;

    cudaFuncSetAttribute(gemm_kernel, cudaFuncAttributeMaxDynamicSharedMemorySize,
                         SMEM_TOTAL);

    prep_kernel<<<UNPACK_BLOCKS + M_DIM, 256>>>(qweight, x);
    gemm_kernel<<<GRID_PERSIST, 128, SMEM_TOTAL>>>(scales, qzeros, bias, out);
}

// round 16
// speedup vs baseline: 1.0449x; 1.0449x over previous
#include <cuda_runtime.h>
#include <cuda_fp16.h>
#include <cstdint>

// ---------------------------------------------------------------------------
// Problem constants
// ---------------------------------------------------------------------------
#define K_DIM 4096
#define N_DIM 11008
#define M_DIM 8192
#define NGC   (N_DIM / 8)          // packed int32 per K row

// GEMM tiling
#define BM 128
#define BN 128
#define BK 64
#define KT (K_DIM / BK)            // 64 k-iterations
#define NSTAGES 3
#define STAGE_A_BYTES (BM * BK * 2)    // 16384
#define STAGE_B_BYTES (BN * BK * 2)    // 16384
#define SMEM_A 0
#define SMEM_B (NSTAGES * STAGE_A_BYTES)                  // 49152
#define SMEM_COEF (SMEM_B + NSTAGES * STAGE_B_BYTES)      // 98304
#define SMEM_TOTAL (SMEM_COEF + 3 * BN * 4)               // 99840

#define NT_TILES (N_DIM / BN)      // 86
#define MT_TILES (M_DIM / BM)      // 64
#define GROUP_M 8

#define UNPACK_BLOCKS ((N_DIM / 256) * (K_DIM / 64))   // 43 * 64 = 2752
#define NB_BLOCKS (N_DIM / 256)                        // 43

// ---------------------------------------------------------------------------
// Device scratch (no allocations allowed in kernel_launch)
// ---------------------------------------------------------------------------
__device__ __align__(1024) __half g_Wt[(size_t)N_DIM * K_DIM];   // W^T [N,K] fp16
__device__ __align__(1024) __half g_Xh[(size_t)M_DIM * K_DIM];   // X   [M,K] fp16
__device__ float g_rowsum[M_DIM];

// ---------------------------------------------------------------------------
// PTX helpers (generic sm_80-level PTX only: compiles under compute_103)
// ---------------------------------------------------------------------------
__device__ __forceinline__ uint32_t smem_u32(const void* p) {
    uint32_t a;
    asm("{ .reg .u64 t; cvta.to.shared.u64 t, %1; cvt.u32.u64 %0, t; }"
        : "=r"(a) : "l"(p));
    return a;
}

__device__ __forceinline__ void cp_async16(uint32_t dst, const void* src) {
    asm volatile("cp.async.cg.shared.global [%0], [%1], 16;"
                 :: "r"(dst), "l"(__cvta_generic_to_global(src)) : "memory");
}
__device__ __forceinline__ void cp_commit() {
    asm volatile("cp.async.commit_group;" ::: "memory");
}
template <int N>
__device__ __forceinline__ void cp_wait() {
    asm volatile("cp.async.wait_group %0;" :: "n"(N) : "memory");
}

__device__ __forceinline__ void ldsm_x4(uint32_t& r0, uint32_t& r1, uint32_t& r2,
                                        uint32_t& r3, uint32_t addr) {
    asm volatile("ldmatrix.sync.aligned.m8n8.x4.shared.b16 {%0,%1,%2,%3}, [%4];"
                 : "=r"(r0), "=r"(r1), "=r"(r2), "=r"(r3) : "r"(addr));
}

__device__ __forceinline__ void mma16816(float* c, const uint32_t* a, const uint32_t* b) {
    asm volatile(
        "mma.sync.aligned.m16n8k16.row.col.f32.f16.f16.f32 "
        "{%0,%1,%2,%3}, {%4,%5,%6,%7}, {%8,%9}, {%0,%1,%2,%3};"
        : "+f"(c[0]), "+f"(c[1]), "+f"(c[2]), "+f"(c[3])
        : "r"(a[0]), "r"(a[1]), "r"(a[2]), "r"(a[3]), "r"(b[0]), "r"(b[1]));
}

// ---------------------------------------------------------------------------
// Kernel 0 (fused prep): blocks [0, UNPACK_BLOCKS) unpack int4 weights ->
// g_Wt[N][K] fp16; blocks [UNPACK_BLOCKS, +M_DIM) convert X fp32 -> fp16 +
// rowsum of the rounded values. Independent work, overlapped on the chip.
// ---------------------------------------------------------------------------
__global__ __launch_bounds__(256) void prep_kernel(const int* __restrict__ qw,
                                                   const float* __restrict__ x) {
    __shared__ int w[64][32];          // 8KB (unpack branch only)
    __shared__ float ws[8];

    if (blockIdx.x < UNPACK_BLOCKS) {
        const int bx = blockIdx.x % NB_BLOCKS;
        const int by = blockIdx.x / NB_BLOCKS;
        const int n0 = bx * 256;
        const int k0 = by * 64;
        const int ngBase = n0 >> 3;
        const int lane = threadIdx.x & 31;
        const int wq = threadIdx.x >> 5;

#pragma unroll
        for (int i = 0; i < 8; i++) {
            const int k = wq * 8 + i;
            w[k][lane] = qw[(size_t)(k0 + k) * NGC + ngBase + lane];
        }
        __syncthreads();

        const int t = threadIdx.x;     // owns output row n0 + t
        const int col = t >> 3;
        const int sh = (t & 7) * 4;
        __half2 buf[32];
#pragma unroll
        for (int k = 0; k < 64; k += 2) {
            const uint32_t q0 = ((uint32_t)w[k][col] >> sh) & 0xF;
            const uint32_t q1 = ((uint32_t)w[k + 1][col] >> sh) & 0xF;
            buf[k >> 1] = __floats2half2_rn((float)q0, (float)q1);
        }
        uint4* dst = reinterpret_cast<uint4*>(g_Wt + (size_t)(n0 + t) * K_DIM + k0);
        const uint4* src = reinterpret_cast<const uint4*>(buf);
#pragma unroll
        for (int i = 0; i < 8; i++) dst[i] = src[i];
    } else {
        const int m = blockIdx.x - UNPACK_BLOCKS;
        const float4* xr = reinterpret_cast<const float4*>(x + (size_t)m * K_DIM);
        uint2* xo = reinterpret_cast<uint2*>(g_Xh + (size_t)m * K_DIM);
        float sum = 0.f;
#pragma unroll
        for (int i = 0; i < 4; i++) {
            const int j = threadIdx.x + i * 256;
            const float4 v = xr[j];
            __half2 a = __floats2half2_rn(v.x, v.y);
            __half2 b = __floats2half2_rn(v.z, v.w);
            uint2 u;
            u.x = *reinterpret_cast<uint32_t*>(&a);
            u.y = *reinterpret_cast<uint32_t*>(&b);
            xo[j] = u;
            const float2 fa = __half22float2(a);
            const float2 fb = __half22float2(b);
            sum += (fa.x + fa.y) + (fb.x + fb.y);
        }
#pragma unroll
        for (int off = 16; off; off >>= 1) sum += __shfl_xor_sync(0xffffffffu, sum, off);
        if ((threadIdx.x & 31) == 0) ws[threadIdx.x >> 5] = sum;
        __syncthreads();
        if (threadIdx.x == 0) {
            float s = 0.f;
#pragma unroll
            for (int wi = 0; wi < 8; wi++) s += ws[wi];
            g_rowsum[m] = s;
        }
    }
}

// ---------------------------------------------------------------------------
// Kernel 1: mma.sync fp16 GEMM, 128x128x64 CTA tile, four 64x64 warps, occ 2,
// one CTA per output tile (grid 5504), 3-stage cp.async pipeline,
// hand-interleaved inner loop (16 sub-blocks of 8 HMMA; ldsm + cp.async
// chunks diffused between them). RACE-FREE tail prefetch: the single
// per-iter __syncthreads sits after ks2, immediately after cp_wait<1> —
// each thread retires its own async groups, the barrier publishes all
// threads' copies, and only then does the tail-prefetch ldmatrix read the
// next stage. The same barrier orders all ldsm reads of the current stage
// (which end in ks2) before the next iteration's refill writes.
// Epilogue: out = acc*scale - rowsum*scale*zp + bias
// ---------------------------------------------------------------------------
__global__ __launch_bounds__(128, 2) void gemm_kernel(
    const float* __restrict__ scales,
    const int*   __restrict__ qzeros,
    const float* __restrict__ bias,
    float* __restrict__ out)
{
    extern __shared__ char smem[];
    const uint32_t sb = smem_u32(smem);
    const int tid = threadIdx.x;
    const int lane = tid & 31;
    const int wid = tid >> 5;           // 0..3

    // CTA swizzle: GROUP_M m-tiles per group for L2 reuse
    const int pid = blockIdx.x;
    const int group = pid / (GROUP_M * NT_TILES);
    const int rem = pid - group * (GROUP_M * NT_TILES);
    const int mt = group * GROUP_M + (rem & (GROUP_M - 1));
    const int nt = rem >> 3;   // GROUP_M == 8
    const int mBase = mt * BM;
    const int nBase = nt * BN;

    // Epilogue coefficients (128 threads cover BN=128 exactly)
    float* sS = reinterpret_cast<float*>(smem + SMEM_COEF);
    float* sZ = sS + BN;
    float* sBi = sZ + BN;
    {
        const int n = nBase + tid;
        const float sc = scales[n];
        const int zq = qzeros[n >> 3];
        const int zp = (zq >> ((n & 7) * 4)) & 0xF;
        sS[tid] = sc;
        sZ[tid] = sc * (float)zp;
        sBi[tid] = bias[n];
    }

    // cp.async indices: 128 threads, 16B chunks; rows of 128B (8 chunks)
    const int ldRow = tid >> 3;          // 0..15
    const int ldChunk = tid & 7;         // 0..7
    const uint32_t swz = (uint32_t)((ldChunk ^ (ldRow & 7)) << 4);

    const __half* gA = g_Xh + (size_t)mBase * K_DIM;
    const __half* gB = g_Wt + (size_t)nBase * K_DIM;

    // Warp tiling: 2 (m) x 2 (n) warps; warp tile 64 x 64
    const int warp_m = wid >> 1;         // 0..1
    const int warp_n = wid & 1;          // 0..1
    const int rowA0 = warp_m * 64 + (lane & 15);
    const int rowB0 = warp_n * 64 + (lane & 15);
    const int halfSel = lane >> 4;

    const uint32_t aAddrBase = sb + SMEM_A + rowA0 * 128;
    const uint32_t bAddrBase = sb + SMEM_B + rowB0 * 128;
    const uint32_t xorA = (uint32_t)(rowA0 & 7);
    const uint32_t xorB = (uint32_t)(rowB0 & 7);

    float acc[4][8][4];
#pragma unroll
    for (int mi = 0; mi < 4; mi++)
#pragma unroll
        for (int nj = 0; nj < 8; nj++)
#pragma unroll
            for (int e = 0; e < 4; e++) acc[mi][nj][e] = 0.f;

    uint32_t afr[2][4][4];
    uint32_t bfr[2][8][2];

    // Single-piece fragment loaders
    auto ldsmA1 = [&](int buf, uint32_t aSt, int ks, int mi) {
        const uint32_t c = (uint32_t)(ks * 2 + halfSel);
        ldsm_x4(afr[buf][mi][0], afr[buf][mi][1], afr[buf][mi][2],
                afr[buf][mi][3], aSt + mi * 16 * 128 + ((c ^ xorA) << 4));
    };
    auto ldsmB1 = [&](int buf, uint32_t bSt, int ks, int ni) {
        const uint32_t c = (uint32_t)(ks * 2 + halfSel);
        uint32_t r0, r1, r2, r3;
        ldsm_x4(r0, r1, r2, r3, bSt + ni * 16 * 128 + ((c ^ xorB) << 4));
        bfr[buf][ni * 2][0] = r0;     bfr[buf][ni * 2][1] = r2;
        bfr[buf][ni * 2 + 1][0] = r1; bfr[buf][ni * 2 + 1][1] = r3;
    };
    // One 16B chunk of a stage fill (i = 0..7 A, 8..15 B)
    auto chunk = [&](int st, int gk, int i) {
        if (i < 8) {
            const int row = ldRow + i * 16;
            cp_async16(sb + SMEM_A + st * STAGE_A_BYTES + row * 128 + swz,
                       gA + (size_t)row * K_DIM + gk);
        } else {
            const int row = ldRow + (i - 8) * 16;
            cp_async16(sb + SMEM_B + st * STAGE_B_BYTES + row * 128 + swz,
                       gB + (size_t)row * K_DIM + gk);
        }
    };
    auto mmaRow = [&](int cb, int mi) {
#pragma unroll
        for (int nj = 0; nj < 8; nj++)
            mma16816(acc[mi][nj], afr[cb][mi], bfr[cb][nj]);
    };

    // Prologue: fill stages 0 and 1; publish; preload (kt=0, ks=0) fragments
#pragma unroll
    for (int i = 0; i < 16; i++) chunk(0, ldChunk * 8, i);
    cp_commit();
#pragma unroll
    for (int i = 0; i < 16; i++) chunk(1, BK + ldChunk * 8, i);
    cp_commit();
    cp_wait<1>();
    __syncthreads();                     // publish stage 0 to all threads
#pragma unroll
    for (int mi = 0; mi < 4; mi++) ldsmA1(0, aAddrBase, 0, mi);
#pragma unroll
    for (int ni = 0; ni < 4; ni++) ldsmB1(0, bAddrBase, 0, ni);

    int stRead = 0;
    int stWrite = NSTAGES - 1;

    for (int kt = 0; kt < KT; kt++) {
        const uint32_t aSt = aAddrBase + stRead * STAGE_A_BYTES;
        const uint32_t bSt = bAddrBase + stRead * STAGE_B_BYTES;
        const int stNext = (stRead == NSTAGES - 1) ? 0 : stRead + 1;
        const uint32_t aNx = aAddrBase + stNext * STAGE_A_BYTES;
        const uint32_t bNx = bAddrBase + stNext * STAGE_B_BYTES;

        const int pf = kt + 2;
        const bool doIss = (pf < KT);
        const int gkk = pf * BK + ldChunk * 8;
        const bool doTail = (kt + 1 < KT);

        // ks0: MMA(buf0) (registers preloaded); ldsm(ks1); A chunks
#pragma unroll
        for (int mi = 0; mi < 4; mi++) {
            mmaRow(0, mi);
            ldsmA1(1, aSt, 1, mi);
            ldsmB1(1, bSt, 1, mi);
            if (doIss) { chunk(stWrite, gkk, 2 * mi); chunk(stWrite, gkk, 2 * mi + 1); }
        }
        // ks1: MMA(buf1); ldsm(ks2); B chunks
#pragma unroll
        for (int mi = 0; mi < 4; mi++) {
            mmaRow(1, mi);
            ldsmA1(0, aSt, 2, mi);
            ldsmB1(0, bSt, 2, mi);
            if (doIss) { chunk(stWrite, gkk, 8 + 2 * mi); chunk(stWrite, gkk, 9 + 2 * mi); }
        }
        cp_commit();                     // one group per iter (may be empty)
        // ks2: MMA(buf0); ldsm(ks3) — last reads of the current stage
#pragma unroll
        for (int mi = 0; mi < 4; mi++) {
            mmaRow(0, mi);
            ldsmA1(1, aSt, 3, mi);
            ldsmB1(1, bSt, 3, mi);
        }

        // --- THE barrier: each thread retires its own async groups
        // (leaving only this iter's group outstanding), then the barrier
        // publishes everyone's copies. The stage for kt+1 is now fully
        // visible, and all reads of stage stRead are complete, so the next
        // iteration's refill may overwrite without a top barrier.
        cp_wait<1>();
        __syncthreads();

        // ks3: MMA(buf1); tail-prefetch next iter's ks0 -> buf0 (race-free)
        mmaRow(1, 0);
        if (doTail) { ldsmA1(0, aNx, 0, 0); ldsmB1(0, bNx, 0, 0); }
#pragma unroll
        for (int mi = 1; mi < 4; mi++) {
            mmaRow(1, mi);
            if (doTail) { ldsmA1(0, aNx, 0, mi); ldsmB1(0, bNx, 0, mi); }
        }

        stRead = stNext;
        stWrite = (stWrite == NSTAGES - 1) ? 0 : stWrite + 1;
    }
    cp_wait<0>();

    // ---- Epilogue ----
    const int groupRow = lane >> 2;
    const int colPair = (lane & 3) * 2;
#pragma unroll
    for (int mi = 0; mi < 4; mi++) {
        const int r0 = mBase + warp_m * 64 + mi * 16 + groupRow;
        const int r1 = r0 + 8;
        const float rs0 = g_rowsum[r0];
        const float rs1 = g_rowsum[r1];
        float* o0 = out + (size_t)r0 * N_DIM + nBase;
        float* o1 = out + (size_t)r1 * N_DIM + nBase;
#pragma unroll
        for (int nj = 0; nj < 8; nj++) {
            const int c = warp_n * 64 + nj * 8 + colPair;
            float2 v0, v1;
            v0.x = acc[mi][nj][0] * sS[c]     - rs0 * sZ[c]     + sBi[c];
            v0.y = acc[mi][nj][1] * sS[c + 1] - rs0 * sZ[c + 1] + sBi[c + 1];
            v1.x = acc[mi][nj][2] * sS[c]     - rs1 * sZ[c]     + sBi[c];
            v1.y = acc[mi][nj][3] * sS[c + 1] - rs1 * sZ[c + 1] + sBi[c + 1];
            *reinterpret_cast<float2*>(o0 + c) = v0;
            *reinterpret_cast<float2*>(o1 + c) = v1;
        }
    }
}

// ---------------------------------------------------------------------------
// Host
// ---------------------------------------------------------------------------
extern "C" void kernel_launch(void* const* d_in, const int* in_sizes, int n_in,
                              void* d_out, int out_size) {
    const float* x       = (const float*)d_in[0];
    const int*   qweight = (const int*)d_in[1];
    const float* scales  = (const float*)d_in[2];
    const int*   qzeros  = (const int*)d_in[3];
    const float* bias    = (const float*)d_in[4];
    float* out = (float*)d_out;

    cudaFuncSetAttribute(gemm_kernel, cudaFuncAttributeMaxDynamicSharedMemorySize,
                         SMEM_TOTAL);

    prep_kernel<<<UNPACK_BLOCKS + M_DIM, 256>>>(qweight, x);
    gemm_kernel<<<MT_TILES * NT_TILES, 128, SMEM_TOTAL>>>(scales, qzeros, bias, out);
}

// round 17
// speedup vs baseline: 1.0529x; 1.0077x over previous
#include <cuda_runtime.h>
#include <cuda_fp16.h>
#include <cstdint>

// ---------------------------------------------------------------------------
// Problem constants
// ---------------------------------------------------------------------------
#define K_DIM 4096
#define N_DIM 11008
#define M_DIM 8192
#define NGC   (N_DIM / 8)          // packed int32 per K row

// GEMM tiling
#define BM 128
#define BN 128
#define BK 64
#define KT (K_DIM / BK)            // 64 k-iterations
#define NSTAGES 3
#define STAGE_A_BYTES (BM * BK * 2)    // 16384
#define STAGE_B_BYTES (BN * BK * 2)    // 16384
#define SMEM_A 0
#define SMEM_B (NSTAGES * STAGE_A_BYTES)                  // 49152
#define SMEM_COEF (SMEM_B + NSTAGES * STAGE_B_BYTES)      // 98304
#define SMEM_TOTAL (SMEM_COEF + 3 * BN * 4)               // 99840

#define NT_TILES (N_DIM / BN)      // 86
#define MT_TILES (M_DIM / BM)      // 64
#define GROUP_M 8

#define UNPACK_BLOCKS ((N_DIM / 256) * (K_DIM / 64))   // 43 * 64 = 2752
#define NB_BLOCKS (N_DIM / 256)                        // 43

// ---------------------------------------------------------------------------
// Device scratch (no allocations allowed in kernel_launch)
// ---------------------------------------------------------------------------
__device__ __align__(1024) __half g_Wt[(size_t)N_DIM * K_DIM];   // W^T [N,K] fp16
__device__ __align__(1024) __half g_Xh[(size_t)M_DIM * K_DIM];   // X   [M,K] fp16
__device__ float g_rowsum[M_DIM];

// ---------------------------------------------------------------------------
// PTX helpers (generic sm_80-level PTX only: compiles under compute_103)
// ---------------------------------------------------------------------------
__device__ __forceinline__ uint32_t smem_u32(const void* p) {
    uint32_t a;
    asm("{ .reg .u64 t; cvta.to.shared.u64 t, %1; cvt.u32.u64 %0, t; }"
        : "=r"(a) : "l"(p));
    return a;
}

__device__ __forceinline__ void cp_async16(uint32_t dst, const void* src) {
    asm volatile("cp.async.cg.shared.global [%0], [%1], 16;"
                 :: "r"(dst), "l"(__cvta_generic_to_global(src)) : "memory");
}
__device__ __forceinline__ void cp_commit() {
    asm volatile("cp.async.commit_group;" ::: "memory");
}
template <int N>
__device__ __forceinline__ void cp_wait() {
    asm volatile("cp.async.wait_group %0;" :: "n"(N) : "memory");
}

__device__ __forceinline__ void ldsm_x4(uint32_t& r0, uint32_t& r1, uint32_t& r2,
                                        uint32_t& r3, uint32_t addr) {
    asm volatile("ldmatrix.sync.aligned.m8n8.x4.shared.b16 {%0,%1,%2,%3}, [%4];"
                 : "=r"(r0), "=r"(r1), "=r"(r2), "=r"(r3) : "r"(addr));
}

__device__ __forceinline__ void mma16816(float* c, const uint32_t* a, const uint32_t* b) {
    asm volatile(
        "mma.sync.aligned.m16n8k16.row.col.f32.f16.f16.f32 "
        "{%0,%1,%2,%3}, {%4,%5,%6,%7}, {%8,%9}, {%0,%1,%2,%3};"
        : "+f"(c[0]), "+f"(c[1]), "+f"(c[2]), "+f"(c[3])
        : "r"(a[0]), "r"(a[1]), "r"(a[2]), "r"(a[3]), "r"(b[0]), "r"(b[1]));
}

// ---------------------------------------------------------------------------
// Kernel 0 (fused prep): blocks [0, UNPACK_BLOCKS) unpack int4 weights ->
// g_Wt[N][K] fp16; blocks [UNPACK_BLOCKS, +M_DIM) convert X fp32 -> fp16 +
// rowsum of the rounded values. Independent work, overlapped on the chip.
// ---------------------------------------------------------------------------
__global__ __launch_bounds__(256) void prep_kernel(const int* __restrict__ qw,
                                                   const float* __restrict__ x) {
    __shared__ int w[64][32];          // 8KB (unpack branch only)
    __shared__ float ws[8];

    if (blockIdx.x < UNPACK_BLOCKS) {
        const int bx = blockIdx.x % NB_BLOCKS;
        const int by = blockIdx.x / NB_BLOCKS;
        const int n0 = bx * 256;
        const int k0 = by * 64;
        const int ngBase = n0 >> 3;
        const int lane = threadIdx.x & 31;
        const int wq = threadIdx.x >> 5;

#pragma unroll
        for (int i = 0; i < 8; i++) {
            const int k = wq * 8 + i;
            w[k][lane] = qw[(size_t)(k0 + k) * NGC + ngBase + lane];
        }
        __syncthreads();

        const int t = threadIdx.x;     // owns output row n0 + t
        const int col = t >> 3;
        const int sh = (t & 7) * 4;
        __half2 buf[32];
#pragma unroll
        for (int k = 0; k < 64; k += 2) {
            const uint32_t q0 = ((uint32_t)w[k][col] >> sh) & 0xF;
            const uint32_t q1 = ((uint32_t)w[k + 1][col] >> sh) & 0xF;
            buf[k >> 1] = __floats2half2_rn((float)q0, (float)q1);
        }
        uint4* dst = reinterpret_cast<uint4*>(g_Wt + (size_t)(n0 + t) * K_DIM + k0);
        const uint4* src = reinterpret_cast<const uint4*>(buf);
#pragma unroll
        for (int i = 0; i < 8; i++) dst[i] = src[i];
    } else {
        const int m = blockIdx.x - UNPACK_BLOCKS;
        const float4* xr = reinterpret_cast<const float4*>(x + (size_t)m * K_DIM);
        uint2* xo = reinterpret_cast<uint2*>(g_Xh + (size_t)m * K_DIM);
        float sum = 0.f;
#pragma unroll
        for (int i = 0; i < 4; i++) {
            const int j = threadIdx.x + i * 256;
            const float4 v = xr[j];
            __half2 a = __floats2half2_rn(v.x, v.y);
            __half2 b = __floats2half2_rn(v.z, v.w);
            uint2 u;
            u.x = *reinterpret_cast<uint32_t*>(&a);
            u.y = *reinterpret_cast<uint32_t*>(&b);
            xo[j] = u;
            const float2 fa = __half22float2(a);
            const float2 fb = __half22float2(b);
            sum += (fa.x + fa.y) + (fb.x + fb.y);
        }
#pragma unroll
        for (int off = 16; off; off >>= 1) sum += __shfl_xor_sync(0xffffffffu, sum, off);
        if ((threadIdx.x & 31) == 0) ws[threadIdx.x >> 5] = sum;
        __syncthreads();
        if (threadIdx.x == 0) {
            float s = 0.f;
#pragma unroll
            for (int wi = 0; wi < 8; wi++) s += ws[wi];
            g_rowsum[m] = s;
        }
    }
}

// ---------------------------------------------------------------------------
// Kernel 1: mma.sync fp16 GEMM, 128x128x64 CTA tile, four 64x64 warps, occ 2,
// one CTA per output tile (grid 5504), 3-stage cp.async pipeline,
// hand-interleaved inner loop. ks3 is split around the sync point so the
// cp_wait<1> is covered by 16 HMMA and the barrier drain by 8 more
// (defer-blocking), with the race-free tail prefetch strictly after the
// publish barrier. All ldsm reads of the current stage end in ks2, before
// the barrier, preserving WAR vs the next iteration's refill.
// Epilogue: out = acc*scale - rowsum*scale*zp + bias
// ---------------------------------------------------------------------------
__global__ __launch_bounds__(128, 2) void gemm_kernel(
    const float* __restrict__ scales,
    const int*   __restrict__ qzeros,
    const float* __restrict__ bias,
    float* __restrict__ out)
{
    extern __shared__ char smem[];
    const uint32_t sb = smem_u32(smem);
    const int tid = threadIdx.x;
    const int lane = tid & 31;
    const int wid = tid >> 5;           // 0..3

    // CTA swizzle: GROUP_M m-tiles per group for L2 reuse
    const int pid = blockIdx.x;
    const int group = pid / (GROUP_M * NT_TILES);
    const int rem = pid - group * (GROUP_M * NT_TILES);
    const int mt = group * GROUP_M + (rem & (GROUP_M - 1));
    const int nt = rem >> 3;   // GROUP_M == 8
    const int mBase = mt * BM;
    const int nBase = nt * BN;

    // Epilogue coefficients (128 threads cover BN=128 exactly)
    float* sS = reinterpret_cast<float*>(smem + SMEM_COEF);
    float* sZ = sS + BN;
    float* sBi = sZ + BN;
    {
        const int n = nBase + tid;
        const float sc = scales[n];
        const int zq = qzeros[n >> 3];
        const int zp = (zq >> ((n & 7) * 4)) & 0xF;
        sS[tid] = sc;
        sZ[tid] = sc * (float)zp;
        sBi[tid] = bias[n];
    }

    // cp.async indices: 128 threads, 16B chunks; rows of 128B (8 chunks)
    const int ldRow = tid >> 3;          // 0..15
    const int ldChunk = tid & 7;         // 0..7
    const uint32_t swz = (uint32_t)((ldChunk ^ (ldRow & 7)) << 4);

    const __half* gA = g_Xh + (size_t)mBase * K_DIM;
    const __half* gB = g_Wt + (size_t)nBase * K_DIM;

    // Warp tiling: 2 (m) x 2 (n) warps; warp tile 64 x 64
    const int warp_m = wid >> 1;         // 0..1
    const int warp_n = wid & 1;          // 0..1
    const int rowA0 = warp_m * 64 + (lane & 15);
    const int rowB0 = warp_n * 64 + (lane & 15);
    const int halfSel = lane >> 4;

    const uint32_t aAddrBase = sb + SMEM_A + rowA0 * 128;
    const uint32_t bAddrBase = sb + SMEM_B + rowB0 * 128;
    const uint32_t xorA = (uint32_t)(rowA0 & 7);
    const uint32_t xorB = (uint32_t)(rowB0 & 7);

    float acc[4][8][4];
#pragma unroll
    for (int mi = 0; mi < 4; mi++)
#pragma unroll
        for (int nj = 0; nj < 8; nj++)
#pragma unroll
            for (int e = 0; e < 4; e++) acc[mi][nj][e] = 0.f;

    uint32_t afr[2][4][4];
    uint32_t bfr[2][8][2];

    // Single-piece fragment loaders
    auto ldsmA1 = [&](int buf, uint32_t aSt, int ks, int mi) {
        const uint32_t c = (uint32_t)(ks * 2 + halfSel);
        ldsm_x4(afr[buf][mi][0], afr[buf][mi][1], afr[buf][mi][2],
                afr[buf][mi][3], aSt + mi * 16 * 128 + ((c ^ xorA) << 4));
    };
    auto ldsmB1 = [&](int buf, uint32_t bSt, int ks, int ni) {
        const uint32_t c = (uint32_t)(ks * 2 + halfSel);
        uint32_t r0, r1, r2, r3;
        ldsm_x4(r0, r1, r2, r3, bSt + ni * 16 * 128 + ((c ^ xorB) << 4));
        bfr[buf][ni * 2][0] = r0;     bfr[buf][ni * 2][1] = r2;
        bfr[buf][ni * 2 + 1][0] = r1; bfr[buf][ni * 2 + 1][1] = r3;
    };
    // One 16B chunk of a stage fill (i = 0..7 A, 8..15 B)
    auto chunk = [&](int st, int gk, int i) {
        if (i < 8) {
            const int row = ldRow + i * 16;
            cp_async16(sb + SMEM_A + st * STAGE_A_BYTES + row * 128 + swz,
                       gA + (size_t)row * K_DIM + gk);
        } else {
            const int row = ldRow + (i - 8) * 16;
            cp_async16(sb + SMEM_B + st * STAGE_B_BYTES + row * 128 + swz,
                       gB + (size_t)row * K_DIM + gk);
        }
    };
    auto mmaRow = [&](int cb, int mi) {
#pragma unroll
        for (int nj = 0; nj < 8; nj++)
            mma16816(acc[mi][nj], afr[cb][mi], bfr[cb][nj]);
    };

    // Prologue: fill stages 0 and 1; publish; preload (kt=0, ks=0) fragments
#pragma unroll
    for (int i = 0; i < 16; i++) chunk(0, ldChunk * 8, i);
    cp_commit();
#pragma unroll
    for (int i = 0; i < 16; i++) chunk(1, BK + ldChunk * 8, i);
    cp_commit();
    cp_wait<1>();
    __syncthreads();                     // publish stage 0 to all threads
#pragma unroll
    for (int mi = 0; mi < 4; mi++) ldsmA1(0, aAddrBase, 0, mi);
#pragma unroll
    for (int ni = 0; ni < 4; ni++) ldsmB1(0, bAddrBase, 0, ni);

    int stRead = 0;
    int stWrite = NSTAGES - 1;

    for (int kt = 0; kt < KT; kt++) {
        const uint32_t aSt = aAddrBase + stRead * STAGE_A_BYTES;
        const uint32_t bSt = bAddrBase + stRead * STAGE_B_BYTES;
        const int stNext = (stRead == NSTAGES - 1) ? 0 : stRead + 1;
        const uint32_t aNx = aAddrBase + stNext * STAGE_A_BYTES;
        const uint32_t bNx = bAddrBase + stNext * STAGE_B_BYTES;

        const int pf = kt + 2;
        const bool doIss = (pf < KT);
        const int gkk = pf * BK + ldChunk * 8;
        const bool doTail = (kt + 1 < KT);

        // ks0: MMA(buf0) (registers preloaded); ldsm(ks1); A chunks
#pragma unroll
        for (int mi = 0; mi < 4; mi++) {
            mmaRow(0, mi);
            ldsmA1(1, aSt, 1, mi);
            ldsmB1(1, bSt, 1, mi);
            if (doIss) { chunk(stWrite, gkk, 2 * mi); chunk(stWrite, gkk, 2 * mi + 1); }
        }
        // ks1: MMA(buf1); ldsm(ks2); B chunks
#pragma unroll
        for (int mi = 0; mi < 4; mi++) {
            mmaRow(1, mi);
            ldsmA1(0, aSt, 2, mi);
            ldsmB1(0, bSt, 2, mi);
            if (doIss) { chunk(stWrite, gkk, 8 + 2 * mi); chunk(stWrite, gkk, 9 + 2 * mi); }
        }
        cp_commit();                     // one group per iter (may be empty)
        // ks2: MMA(buf0); ldsm(ks3) — LAST reads of the current stage
#pragma unroll
        for (int mi = 0; mi < 4; mi++) {
            mmaRow(0, mi);
            ldsmA1(1, aSt, 3, mi);
            ldsmB1(1, bSt, 3, mi);
        }

        // ks3a: two register-only MMA rows cover the cp_wait pipeline stall
        mmaRow(1, 0);
        mmaRow(1, 1);

        // Retire own async groups (1 outstanding = this iter's), publish all
        // threads' copies. Stage for kt+1 fully visible after this point;
        // all reads of stage stRead are complete (ks2), so next iteration's
        // refill may overwrite it.
        cp_wait<1>();
        __syncthreads();

        // ks3b: one more MMA row issues during barrier drain (defer-block),
        // then the race-free tail prefetch, then the final row.
        mmaRow(1, 2);
        if (doTail) {
            ldsmA1(0, aNx, 0, 0); ldsmB1(0, bNx, 0, 0);
            ldsmA1(0, aNx, 0, 1); ldsmB1(0, bNx, 0, 1);
            ldsmA1(0, aNx, 0, 2); ldsmB1(0, bNx, 0, 2);
            ldsmA1(0, aNx, 0, 3); ldsmB1(0, bNx, 0, 3);
        }
        mmaRow(1, 3);

        stRead = stNext;
        stWrite = (stWrite == NSTAGES - 1) ? 0 : stWrite + 1;
    }
    cp_wait<0>();

    // ---- Epilogue ----
    const int groupRow = lane >> 2;
    const int colPair = (lane & 3) * 2;
#pragma unroll
    for (int mi = 0; mi < 4; mi++) {
        const int r0 = mBase + warp_m * 64 + mi * 16 + groupRow;
        const int r1 = r0 + 8;
        const float rs0 = g_rowsum[r0];
        const float rs1 = g_rowsum[r1];
        float* o0 = out + (size_t)r0 * N_DIM + nBase;
        float* o1 = out + (size_t)r1 * N_DIM + nBase;
#pragma unroll
        for (int nj = 0; nj < 8; nj++) {
            const int c = warp_n * 64 + nj * 8 + colPair;
            float2 v0, v1;
            v0.x = acc[mi][nj][0] * sS[c]     - rs0 * sZ[c]     + sBi[c];
            v0.y = acc[mi][nj][1] * sS[c + 1] - rs0 * sZ[c + 1] + sBi[c + 1];
            v1.x = acc[mi][nj][2] * sS[c]     - rs1 * sZ[c]     + sBi[c];
            v1.y = acc[mi][nj][3] * sS[c + 1] - rs1 * sZ[c + 1] + sBi[c + 1];
            *reinterpret_cast<float2*>(o0 + c) = v0;
            *reinterpret_cast<float2*>(o1 + c) = v1;
        }
    }
}

// ---------------------------------------------------------------------------
// Host
// ---------------------------------------------------------------------------
extern "C" void kernel_launch(void* const* d_in, const int* in_sizes, int n_in,
                              void* d_out, int out_size) {
    const float* x       = (const float*)d_in[0];
    const int*   qweight = (const int*)d_in[1];
    const float* scales  = (const float*)d_in[2];
    const int*   qzeros  = (const int*)d_in[3];
    const float* bias    = (const float*)d_in[4];
    float* out = (float*)d_out;

    cudaFuncSetAttribute(gemm_kernel, cudaFuncAttributeMaxDynamicSharedMemorySize,
                         SMEM_TOTAL);

    prep_kernel<<<UNPACK_BLOCKS + M_DIM, 256>>>(qweight, x);
    gemm_kernel<<<MT_TILES * NT_TILES, 128, SMEM_TOTAL>>>(scales, qzeros, bias, out);
}